// round 11
// baseline (speedup 1.0000x reference)
#include <cuda_runtime.h>
#include <math.h>

#define Nn   50000
#define Ee   500000
#define FIN  64
#define EIN  16
#define Hh   100
#define LL   2
#define BN_EPS 1e-5f

// ---------------- scratch (static device globals; no allocation) -------------
__device__ float g_h   [Nn * Hh];
__device__ float g_e   [(size_t)Ee * Hh];
__device__ float g_agg [Nn * Hh];
__device__ float g_zin [Nn * Hh];
__device__ float g_t   [Nn * Hh];
__device__ float g_z   [Nn * Hh];
__device__ float g_Ha  [Nn * Hh];
__device__ float g_Hb  [Nn * Hh];
__device__ float g_HRa [Nn * 50];
__device__ float g_HRb [Nn * 50];
__device__ float g_o1  [(size_t)Ee * 50];
__device__ float g_stats[2 * Hh];

// ---------------- small kernels ----------------------------------------------
__global__ void zero2_k(float* __restrict__ agg, float* __restrict__ st) {
    int i = blockIdx.x * blockDim.x + threadIdx.x;
    if (i < Nn * Hh) agg[i] = 0.f;
    if (i < 2 * Hh) st[i] = 0.f;
}

__global__ void add_k(const float* __restrict__ a, const float* __restrict__ b,
                      float* __restrict__ c, int n) {
    int i = blockIdx.x * blockDim.x + threadIdx.x;
    if (i < n) c[i] = a[i] + b[i];
}

__global__ void relu_k(const float* __restrict__ a, float* __restrict__ c, int n) {
    int i = blockIdx.x * blockDim.x + threadIdx.x;
    if (i < n) c[i] = fmaxf(a[i], 0.f);
}

__global__ void __launch_bounds__(256)
scatter_k(const float* __restrict__ h, const float* __restrict__ e,
          const int* __restrict__ src, const int* __restrict__ dst,
          float* __restrict__ agg) {
    int ed = blockIdx.x * 8 + (threadIdx.x >> 5);
    int lane = threadIdx.x & 31;
    if (lane >= 25) return;
    int s = src[ed], d = dst[ed];
    float4 hv = ((const float4*)(h + (size_t)s * Hh))[lane];
    float4 ev = ((const float4*)(e + (size_t)ed * Hh))[lane];
    float* ar = agg + (size_t)d * Hh + 4 * lane;
    float m0 = hv.x + ev.x, m1 = hv.y + ev.y, m2 = hv.z + ev.z, m3 = hv.w + ev.w;
    if (m0 > 0.f) atomicAdd(ar + 0, m0);
    if (m1 > 0.f) atomicAdd(ar + 1, m1);
    if (m2 > 0.f) atomicAdd(ar + 2, m2);
    if (m3 > 0.f) atomicAdd(ar + 3, m3);
}

__global__ void bn_stats_k(const float* __restrict__ z, float* __restrict__ stats) {
    int j = threadIdx.x;
    if (j >= Hh) return;
    int r0 = blockIdx.x * 256;
    int r1 = min(r0 + 256, Nn);
    float s = 0.f, ss = 0.f;
    for (int r = r0; r < r1; r++) {
        float v = z[(size_t)r * Hh + j];
        s += v;
        ss = fmaf(v, v, ss);
    }
    atomicAdd(&stats[j], s);
    atomicAdd(&stats[Hh + j], ss);
}

__global__ void hupd_k(float* __restrict__ h, const float* __restrict__ z,
                       const float* __restrict__ stats,
                       const float* __restrict__ gamma, const float* __restrict__ beta) {
    int idx = blockIdx.x * blockDim.x + threadIdx.x;
    if (idx >= Nn * Hh) return;
    int j = idx % Hh;
    float mu  = stats[j] * (1.0f / Nn);
    float var = fmaf(-mu, mu, stats[Hh + j] * (1.0f / Nn));
    float zn  = (z[idx] - mu) * rsqrtf(var + BN_EPS) * gamma[j] + beta[j];
    h[idx] = (h[idx] + fmaxf(zn, 0.f)) * 0.5f;
}

// ---------------- TF32 helpers -----------------------------------------------
__device__ __forceinline__ unsigned f2tf(float f) {
    unsigned u;
    asm("cvt.rna.tf32.f32 %0, %1;" : "=r"(u) : "f"(f));
    return u;
}

__device__ __forceinline__ void mma8(float* c, unsigned a0, unsigned a1,
                                     unsigned a2, unsigned a3,
                                     unsigned b0, unsigned b1) {
    asm volatile(
        "mma.sync.aligned.m16n8k8.row.col.f32.tf32.tf32.f32 "
        "{%0,%1,%2,%3}, {%4,%5,%6,%7}, {%8,%9}, {%0,%1,%2,%3};"
        : "+f"(c[0]), "+f"(c[1]), "+f"(c[2]), "+f"(c[3])
        : "r"(a0), "r"(a1), "r"(a2), "r"(a3), "r"(b0), "r"(b1));
}

// pack W fragments with hi/lo split: float4 {b0hi, b1hi, b0lo, b1lo}
template<int KIN, int KST, int NT, int NV, int NTHR>
__device__ __forceinline__ void pack_w(const float* __restrict__ W, float* Wp, int tid) {
    for (int idx = tid; idx < KST * NT * 32; idx += NTHR) {
        int ks  = idx / (NT * 32);
        int rem = idx - ks * NT * 32;
        int nt = rem >> 5, l = rem & 31;
        int k0 = ks * 8 + (l & 3), n = nt * 8 + (l >> 2);
        float w0 = (k0 < KIN && n < NV) ? W[k0 * NV + n] : 0.f;
        float w1 = (k0 + 4 < KIN && n < NV) ? W[(k0 + 4) * NV + n] : 0.f;
        unsigned h0 = f2tf(w0), h1 = f2tf(w1);
        unsigned l0 = f2tf(w0 - __uint_as_float(h0));
        unsigned l1 = f2tf(w1 - __uint_as_float(h1));
        ((float4*)Wp)[idx] = make_float4(__uint_as_float(h0), __uint_as_float(h1),
                                         __uint_as_float(l0), __uint_as_float(l1));
    }
}

// 3-term TF32 mainloop: acc[NT][4] += A(16 rows) @ W-frags
template<int KST, int KP, int NT>
__device__ __forceinline__ void mma_main(const float* __restrict__ Ab,
                                         const float* __restrict__ Wp,
                                         int lane, float acc[][4]) {
    const int g = lane >> 2, tg = lane & 3;
    #pragma unroll
    for (int ks = 0; ks < KST; ks++) {
        float f0 = Ab[g * KP + ks * 8 + tg];
        float f1 = Ab[(g + 8) * KP + ks * 8 + tg];
        float f2 = Ab[g * KP + ks * 8 + tg + 4];
        float f3 = Ab[(g + 8) * KP + ks * 8 + tg + 4];
        unsigned ah0 = f2tf(f0), ah1 = f2tf(f1), ah2 = f2tf(f2), ah3 = f2tf(f3);
        unsigned al0 = f2tf(f0 - __uint_as_float(ah0));
        unsigned al1 = f2tf(f1 - __uint_as_float(ah1));
        unsigned al2 = f2tf(f2 - __uint_as_float(ah2));
        unsigned al3 = f2tf(f3 - __uint_as_float(ah3));
        const float4* wrow = (const float4*)Wp + ks * NT * 32 + lane;
        float4 b[NT];
        #pragma unroll
        for (int nt = 0; nt < NT; nt++) b[nt] = wrow[nt * 32];
        #pragma unroll
        for (int nt = 0; nt < NT; nt++)
            mma8(acc[nt], ah0, ah1, ah2, ah3,
                 __float_as_uint(b[nt].x), __float_as_uint(b[nt].y));
        #pragma unroll
        for (int nt = 0; nt < NT; nt++)
            mma8(acc[nt], al0, al1, al2, al3,
                 __float_as_uint(b[nt].x), __float_as_uint(b[nt].y));
        #pragma unroll
        for (int nt = 0; nt < NT; nt++)
            mma8(acc[nt], ah0, ah1, ah2, ah3,
                 __float_as_uint(b[nt].z), __float_as_uint(b[nt].w));
    }
}

// async copy of one 128/64-row A tile; zero-fills pad + OOB rows
template<int KIN, int KP, int ROWS, int NTHR>
__device__ __forceinline__ void prefetch_tile(const float* __restrict__ A, int M,
                                              int t, float* db, int tid) {
    constexpr int CH = KP / 4;
    const int row0 = t * ROWS;
    for (int idx = tid; idx < ROWS * CH; idx += NTHR) {
        int r = idx / CH, c = idx - r * CH;
        int grow = row0 + r;
        unsigned sa = (unsigned)__cvta_generic_to_shared(db + r * KP + c * 4);
        int nb = 0;
        const float* gs = A;
        if (grow < M) {
            int col = c * 4;
            nb = KIN - col;
            nb = nb < 0 ? 0 : (nb > 4 ? 4 : nb);
            nb *= 4;
            gs = A + (size_t)grow * KIN + (col < KIN ? col : 0);
        }
        asm volatile("cp.async.cg.shared.global [%0], [%1], 16, %2;"
                     :: "r"(sa), "l"(gs), "r"(nb));
    }
    asm volatile("cp.async.commit_group;");
}

// ---------------- standard TF32 GEMM (256 thr, 128-row tiles, dbl-buffered) --
// EPI: 0 store+bias, 1 relu(acc+bias), 3 relu(acc+bias+Ta[src]+Tb[dst]), 4 raw
template<int KIN, int KST, int KP, int NT, int NV, int EPI>
__global__ void __launch_bounds__(256)
tgemm_k(const float* __restrict__ A, const float* __restrict__ W,
        const float* __restrict__ bias, float* __restrict__ C, int M,
        const int* __restrict__ src, const int* __restrict__ dst,
        const float* __restrict__ Ta, const float* __restrict__ Tb) {
    constexpr int WFRAG = KST * NT * 128;
    constexpr int ATILE = 128 * KP;
    extern __shared__ float sm[];
    float* Wp = sm;
    float* As = sm + WFRAG;
    const int tid  = threadIdx.x;
    const int lane = tid & 31, warp = tid >> 5;
    const int g = lane >> 2, tg = lane & 3;

    pack_w<KIN, KST, NT, NV, 256>(W, Wp, tid);

    const int ntile = (M + 127) >> 7;
    if (blockIdx.x >= ntile) return;
    prefetch_tile<KIN, KP, 128, 256>(A, M, blockIdx.x, As, tid);
    __syncthreads();

    int buf = 0;
    for (int t = blockIdx.x; t < ntile; t += gridDim.x) {
        int tn = t + gridDim.x;
        if (tn < ntile) {
            prefetch_tile<KIN, KP, 128, 256>(A, M, tn, As + (buf ^ 1) * ATILE, tid);
            asm volatile("cp.async.wait_group 1;");
        } else {
            asm volatile("cp.async.wait_group 0;");
        }
        __syncthreads();

        const float* Ab = As + buf * ATILE + warp * 16 * KP;
        float acc[NT][4];
        #pragma unroll
        for (int nt = 0; nt < NT; nt++)
            acc[nt][0] = acc[nt][1] = acc[nt][2] = acc[nt][3] = 0.f;

        mma_main<KST, KP, NT>(Ab, Wp, lane, acc);

        int rbase = t * 128 + warp * 16;
        #pragma unroll
        for (int half = 0; half < 2; half++) {
            int row = rbase + g + half * 8;
            bool rok = row < M;
            const float* ta = nullptr; const float* tb = nullptr;
            if (EPI == 3 && rok) {
                ta = Ta + (size_t)src[row] * NV;
                tb = Tb + (size_t)dst[row] * NV;
            }
            #pragma unroll
            for (int nt = 0; nt < NT; nt++) {
                int n = nt * 8 + tg * 2;
                if (rok && n < NV) {
                    float v0 = acc[nt][half * 2 + 0];
                    float v1 = acc[nt][half * 2 + 1];
                    float2* cp = (float2*)(C + (size_t)row * NV + n);
                    if (EPI == 0) {
                        float2 bs = *(const float2*)(bias + n);
                        *cp = make_float2(v0 + bs.x, v1 + bs.y);
                    } else if (EPI == 1) {
                        float2 bs = *(const float2*)(bias + n);
                        *cp = make_float2(fmaxf(v0 + bs.x, 0.f), fmaxf(v1 + bs.y, 0.f));
                    } else if (EPI == 3) {
                        float2 bs = *(const float2*)(bias + n);
                        float2 tav = *(const float2*)(ta + n);
                        float2 tbv = *(const float2*)(tb + n);
                        *cp = make_float2(fmaxf(v0 + bs.x + tav.x + tbv.x, 0.f),
                                          fmaxf(v1 + bs.y + tav.y + tbv.y, 0.f));
                    } else {
                        *cp = make_float2(v0, v1);
                    }
                }
            }
        }
        buf ^= 1;
        __syncthreads();
    }
}

// ---------------- fused edge-update double GEMM ------------------------------
// t = relu(e@W1 + b1 + Ha[src] + Hb[dst])  (smem only)
// e += 0.5 * (t@W2 + b2)
// 128 threads, 64-row tiles; W1/W2 frags packed once; next-A prefetch overlaps GEMM2.
__global__ void __launch_bounds__(128)
fgemm_k(const float* __restrict__ W1, const float* __restrict__ b1,
        const float* __restrict__ W2, const float* __restrict__ b2,
        float* __restrict__ e,
        const int* __restrict__ src, const int* __restrict__ dst,
        const float* __restrict__ Ta, const float* __restrict__ Tb) {
    constexpr int KST = 13, KP = 108, NT = 13, NV = 100, M = Ee;
    constexpr int WFRAG = KST * NT * 128;
    extern __shared__ float sm[];
    float* Wp1 = sm;
    float* Wp2 = sm + WFRAG;
    float* As  = sm + 2 * WFRAG;            // 64*108
    float* Ts  = sm + 2 * WFRAG + 64 * KP;  // 64*108
    const int tid  = threadIdx.x;
    const int lane = tid & 31, warp = tid >> 5;
    const int g = lane >> 2, tg = lane & 3;

    pack_w<100, KST, NT, NV, 128>(W1, Wp1, tid);
    pack_w<100, KST, NT, NV, 128>(W2, Wp2, tid);

    const int ntile = (M + 63) >> 6;
    prefetch_tile<100, KP, 64, 128>(e, M, blockIdx.x, As, tid);
    __syncthreads();

    for (int t = blockIdx.x; t < ntile; t += gridDim.x) {
        asm volatile("cp.async.wait_group 0;");
        __syncthreads();

        const float* Ab = As + warp * 16 * KP;
        float acc[NT][4];
        #pragma unroll
        for (int nt = 0; nt < NT; nt++)
            acc[nt][0] = acc[nt][1] = acc[nt][2] = acc[nt][3] = 0.f;
        mma_main<KST, KP, NT>(Ab, Wp1, lane, acc);
        __syncthreads();   // all warps done reading As

        // prefetch next tile into As (overlaps t-write + GEMM2)
        int tn = t + gridDim.x;
        if (tn < ntile) prefetch_tile<100, KP, 64, 128>(e, M, tn, As, tid);

        // t tile into Ts (+ gathers + bias + relu); zero K-pad cols
        int rbase = t * 64 + warp * 16;
        #pragma unroll
        for (int half = 0; half < 2; half++) {
            int rl = warp * 16 + g + half * 8;
            int row = rbase + g + half * 8;
            bool rok = row < M;
            const float* ta = nullptr; const float* tb = nullptr;
            if (rok) {
                ta = Ta + (size_t)src[row] * NV;
                tb = Tb + (size_t)dst[row] * NV;
            }
            #pragma unroll
            for (int nt = 0; nt < NT; nt++) {
                int n = nt * 8 + tg * 2;
                if (n < NV) {
                    float v0 = 0.f, v1 = 0.f;
                    if (rok) {
                        float2 bs = *(const float2*)(b1 + n);
                        float2 tav = *(const float2*)(ta + n);
                        float2 tbv = *(const float2*)(tb + n);
                        v0 = fmaxf(acc[nt][half * 2 + 0] + bs.x + tav.x + tbv.x, 0.f);
                        v1 = fmaxf(acc[nt][half * 2 + 1] + bs.y + tav.y + tbv.y, 0.f);
                    }
                    *(float2*)(Ts + rl * KP + n) = make_float2(v0, v1);
                }
            }
        }
        for (int idx = tid; idx < 64 * 8; idx += 128) {
            int r = idx >> 3, c = 100 + (idx & 7);
            Ts[r * KP + c] = 0.f;
        }
        __syncthreads();

        const float* Tb2 = Ts + warp * 16 * KP;
        float acc2[NT][4];
        #pragma unroll
        for (int nt = 0; nt < NT; nt++)
            acc2[nt][0] = acc2[nt][1] = acc2[nt][2] = acc2[nt][3] = 0.f;
        mma_main<KST, KP, NT>(Tb2, Wp2, lane, acc2);

        // epilogue: e[row] += 0.5*(acc2 + b2)
        #pragma unroll
        for (int half = 0; half < 2; half++) {
            int row = rbase + g + half * 8;
            if (row < M) {
                #pragma unroll
                for (int nt = 0; nt < NT; nt++) {
                    int n = nt * 8 + tg * 2;
                    if (n < NV) {
                        float2 bs = *(const float2*)(b2 + n);
                        float2* cp = (float2*)(e + (size_t)row * NV + n);
                        float2 old = *cp;
                        *cp = make_float2(
                            fmaf(0.5f, acc2[nt][half * 2 + 0] + bs.x, old.x),
                            fmaf(0.5f, acc2[nt][half * 2 + 1] + bs.y, old.y));
                    }
                }
            }
        }
        __syncthreads();
    }
}

// fused tail: out = relu(o1@w2+b2) @ w3 + b3 per edge
__global__ void __launch_bounds__(256)
final_fused_k(const float* __restrict__ o1,
              const float* __restrict__ w2, const float* __restrict__ b2,
              const float* __restrict__ w3, const float* __restrict__ b3,
              float* __restrict__ out) {
    __shared__ float sw2[50 * 25];
    __shared__ float sw3[50];
    __shared__ float sb2[25];
    __shared__ float sb3[2];
    int t = threadIdx.x;
    for (int i = t; i < 1250; i += 256) sw2[i] = w2[i];
    if (t < 50) sw3[t] = w3[t];
    if (t < 25) sb2[t] = b2[t];
    if (t < 2)  sb3[t] = b3[t];
    __syncthreads();
    int r = blockIdx.x * 256 + t;
    if (r >= Ee) return;
    float a[50];
    const float2* row = (const float2*)(o1 + (size_t)r * 50);
    #pragma unroll
    for (int i = 0; i < 25; i++) { float2 v = row[i]; a[2*i] = v.x; a[2*i+1] = v.y; }
    float out0 = sb3[0], out1 = sb3[1];
    #pragma unroll 5
    for (int j = 0; j < 25; j++) {
        float s = sb2[j];
        #pragma unroll
        for (int k = 0; k < 50; k++) s = fmaf(a[k], sw2[k * 25 + j], s);
        s = fmaxf(s, 0.f);
        out0 = fmaf(s, sw3[2 * j],     out0);
        out1 = fmaf(s, sw3[2 * j + 1], out1);
    }
    out[(size_t)r * 2]     = out0;
    out[(size_t)r * 2 + 1] = out1;
}

// ---------------- launcher ---------------------------------------------------
static inline int cdiv(int a, int b) { return (a + b - 1) / b; }

template<int KIN, int KST, int KP, int NT, int NV, int EPI>
static void launch_tgemm(int M, const float* A, const float* W,
                         const float* bias, float* C,
                         const int* src = nullptr, const int* dst = nullptr,
                         const float* Ta = nullptr, const float* Tb = nullptr) {
    int smem = (KST * NT * 128 + 2 * 128 * KP) * 4;
    cudaFuncSetAttribute(tgemm_k<KIN, KST, KP, NT, NV, EPI>,
                         cudaFuncAttributeMaxDynamicSharedMemorySize, smem);
    int ntile = cdiv(M, 128);
    int grid = ntile < 148 ? ntile : 148;
    tgemm_k<KIN, KST, KP, NT, NV, EPI><<<grid, 256, smem>>>(
        A, W, bias, C, M, src, dst, Ta, Tb);
}

extern "C" void kernel_launch(void* const* d_in, const int* in_sizes, int n_in,
                              void* d_out, int out_size) {
    const float* x        = (const float*)d_in[0];
    const float* edge_attr= (const float*)d_in[1];
    const int*   ei       = (const int*)  d_in[2];
    const float* node_w   = (const float*)d_in[3];
    const float* node_b   = (const float*)d_in[4];
    const float* edge_w   = (const float*)d_in[5];
    const float* edge_b   = (const float*)d_in[6];
    const float* gw1      = (const float*)d_in[7];
    const float* gb1      = (const float*)d_in[8];
    const float* gw2      = (const float*)d_in[9];
    const float* gb2      = (const float*)d_in[10];
    const float* bng      = (const float*)d_in[11];
    const float* bnb      = (const float*)d_in[12];
    const float* ew1      = (const float*)d_in[13];
    const float* eb1      = (const float*)d_in[14];
    const float* ew2      = (const float*)d_in[15];
    const float* eb2      = (const float*)d_in[16];
    const float* mw1      = (const float*)d_in[17];
    const float* mb1      = (const float*)d_in[18];
    const float* mw2      = (const float*)d_in[19];
    const float* mb2      = (const float*)d_in[20];
    const float* mw3      = (const float*)d_in[21];
    const float* mb3      = (const float*)d_in[22];
    float* out = (float*)d_out;

    void* p;
    cudaGetSymbolAddress(&p, g_h);    float* h    = (float*)p;
    cudaGetSymbolAddress(&p, g_e);    float* e    = (float*)p;
    cudaGetSymbolAddress(&p, g_agg);  float* agg  = (float*)p;
    cudaGetSymbolAddress(&p, g_zin);  float* zin  = (float*)p;
    cudaGetSymbolAddress(&p, g_t);    float* t    = (float*)p;
    cudaGetSymbolAddress(&p, g_z);    float* z    = (float*)p;
    cudaGetSymbolAddress(&p, g_Ha);   float* Ha   = (float*)p;
    cudaGetSymbolAddress(&p, g_Hb);   float* Hb   = (float*)p;
    cudaGetSymbolAddress(&p, g_HRa);  float* HRa  = (float*)p;
    cudaGetSymbolAddress(&p, g_HRb);  float* HRb  = (float*)p;
    cudaGetSymbolAddress(&p, g_o1);   float* o1   = (float*)p;
    cudaGetSymbolAddress(&p, g_stats);float* st   = (float*)p;

    const int* src = ei;
    const int* dst = ei + Ee;

    zero2_k<<<cdiv(Nn * Hh, 256), 256>>>(agg, st);
    launch_tgemm<FIN, 8, 68, 13, 100, 0>(Nn, x, node_w, node_b, h);
    launch_tgemm<EIN, 2, 20, 13, 100, 0>(Ee, edge_attr, edge_w, edge_b, e);

    for (int l = 0; l < LL; l++) {
        if (l > 0) zero2_k<<<cdiv(Nn * Hh, 256), 256>>>(agg, st);
        scatter_k<<<Ee / 8, 256>>>(h, e, src, dst, agg);
        add_k<<<cdiv(Nn * Hh, 256), 256>>>(h, agg, zin, Nn * Hh);
        // GINE MLP (launch 6 on first layer -> profiled)
        launch_tgemm<100, 13, 108, 13, 100, 1>(Nn, zin, gw1 + (size_t)l * 10000,
                                               gb1 + l * Hh, t);
        launch_tgemm<100, 13, 108, 13, 100, 0>(Nn, t, gw2 + (size_t)l * 10000,
                                               gb2 + l * Hh, z);
        bn_stats_k<<<cdiv(Nn, 256), 128>>>(z, st);
        hupd_k<<<cdiv(Nn * Hh, 256), 256>>>(h, z, st, bng + l * Hh, bnb + l * Hh);
        // node-level halves of edge MLP
        launch_tgemm<100, 13, 108, 13, 100, 4>(Nn, h, ew1 + (size_t)l * 30000, nullptr, Ha);
        launch_tgemm<100, 13, 108, 13, 100, 4>(Nn, h, ew1 + (size_t)l * 30000 + 10000, nullptr, Hb);
        // fused: t = relu(e@Wc + Ha[src] + Hb[dst] + b1); e += 0.5*(t@W2 + b2)
        {
            int smem = (2 * 13 * 13 * 128 + 2 * 64 * 108) * 4;
            cudaFuncSetAttribute(fgemm_k, cudaFuncAttributeMaxDynamicSharedMemorySize, smem);
            fgemm_k<<<148, 128, smem>>>(ew1 + (size_t)l * 30000 + 20000, eb1 + l * Hh,
                                        ew2 + (size_t)l * 10000, eb2 + l * Hh,
                                        e, src, dst, Ha, Hb);
        }
    }

    // readout
    relu_k<<<cdiv(Nn * Hh, 256), 256>>>(h, zin, Nn * Hh);
    launch_tgemm<100, 13, 108, 7, 50, 4>(Nn, zin, mw1,        nullptr, HRa);
    launch_tgemm<100, 13, 108, 7, 50, 4>(Nn, zin, mw1 + 5000, nullptr, HRb);
    launch_tgemm<100, 13, 108, 7, 50, 3>(Ee, e, mw1 + 10000, mb1, o1, src, dst, HRa, HRb);
    final_fused_k<<<cdiv(Ee, 256), 256>>>(o1, mw2, mb2, mw3, mb3, out);
}

// round 12
// speedup vs baseline: 1.0018x; 1.0018x over previous
#include <cuda_runtime.h>
#include <math.h>

#define Nn   50000
#define Ee   500000
#define FIN  64
#define EIN  16
#define Hh   100
#define LL   2
#define BN_EPS 1e-5f

// ---------------- scratch (static device globals; no allocation) -------------
__device__ float g_h   [Nn * Hh];
__device__ float g_e   [(size_t)Ee * Hh];
__device__ float g_agg [Nn * Hh];
__device__ float g_zin [Nn * Hh];
__device__ float g_t   [Nn * Hh];
__device__ float g_z   [Nn * Hh];
__device__ float g_Ha  [Nn * Hh];
__device__ float g_Hb  [Nn * Hh];
__device__ float g_HRa [Nn * 50];
__device__ float g_HRb [Nn * 50];
__device__ float g_o1  [(size_t)Ee * 50];
__device__ float g_stats[2 * Hh];

// ---------------- small kernels ----------------------------------------------
__global__ void zero2_k(float* __restrict__ agg, float* __restrict__ st) {
    int i = blockIdx.x * blockDim.x + threadIdx.x;
    if (i < Nn * Hh) agg[i] = 0.f;
    if (i < 2 * Hh) st[i] = 0.f;
}

__global__ void add_k(const float* __restrict__ a, const float* __restrict__ b,
                      float* __restrict__ c, int n) {
    int i = blockIdx.x * blockDim.x + threadIdx.x;
    if (i < n) c[i] = a[i] + b[i];
}

__global__ void relu_k(const float* __restrict__ a, float* __restrict__ c, int n) {
    int i = blockIdx.x * blockDim.x + threadIdx.x;
    if (i < n) c[i] = fmaxf(a[i], 0.f);
}

__global__ void __launch_bounds__(256)
scatter_k(const float* __restrict__ h, const float* __restrict__ e,
          const int* __restrict__ src, const int* __restrict__ dst,
          float* __restrict__ agg) {
    int ed = blockIdx.x * 8 + (threadIdx.x >> 5);
    int lane = threadIdx.x & 31;
    if (lane >= 25) return;
    int s = src[ed], d = dst[ed];
    float4 hv = ((const float4*)(h + (size_t)s * Hh))[lane];
    float4 ev = ((const float4*)(e + (size_t)ed * Hh))[lane];
    float* ar = agg + (size_t)d * Hh + 4 * lane;
    float m0 = hv.x + ev.x, m1 = hv.y + ev.y, m2 = hv.z + ev.z, m3 = hv.w + ev.w;
    if (m0 > 0.f) atomicAdd(ar + 0, m0);
    if (m1 > 0.f) atomicAdd(ar + 1, m1);
    if (m2 > 0.f) atomicAdd(ar + 2, m2);
    if (m3 > 0.f) atomicAdd(ar + 3, m3);
}

__global__ void bn_stats_k(const float* __restrict__ z, float* __restrict__ stats) {
    int j = threadIdx.x;
    if (j >= Hh) return;
    int r0 = blockIdx.x * 256;
    int r1 = min(r0 + 256, Nn);
    float s = 0.f, ss = 0.f;
    for (int r = r0; r < r1; r++) {
        float v = z[(size_t)r * Hh + j];
        s += v;
        ss = fmaf(v, v, ss);
    }
    atomicAdd(&stats[j], s);
    atomicAdd(&stats[Hh + j], ss);
}

__global__ void hupd_k(float* __restrict__ h, const float* __restrict__ z,
                       const float* __restrict__ stats,
                       const float* __restrict__ gamma, const float* __restrict__ beta) {
    int idx = blockIdx.x * blockDim.x + threadIdx.x;
    if (idx >= Nn * Hh) return;
    int j = idx % Hh;
    float mu  = stats[j] * (1.0f / Nn);
    float var = fmaf(-mu, mu, stats[Hh + j] * (1.0f / Nn));
    float zn  = (z[idx] - mu) * rsqrtf(var + BN_EPS) * gamma[j] + beta[j];
    h[idx] = (h[idx] + fmaxf(zn, 0.f)) * 0.5f;
}

// ---------------- TF32 helpers -----------------------------------------------
__device__ __forceinline__ unsigned f2tf(float f) {
    unsigned u;
    asm("cvt.rna.tf32.f32 %0, %1;" : "=r"(u) : "f"(f));
    return u;
}

__device__ __forceinline__ void mma8(float* c, unsigned a0, unsigned a1,
                                     unsigned a2, unsigned a3,
                                     unsigned b0, unsigned b1) {
    asm volatile(
        "mma.sync.aligned.m16n8k8.row.col.f32.tf32.tf32.f32 "
        "{%0,%1,%2,%3}, {%4,%5,%6,%7}, {%8,%9}, {%0,%1,%2,%3};"
        : "+f"(c[0]), "+f"(c[1]), "+f"(c[2]), "+f"(c[3])
        : "r"(a0), "r"(a1), "r"(a2), "r"(a3), "r"(b0), "r"(b1));
}

// pack W fragments with hi/lo split: float4 {b0hi, b1hi, b0lo, b1lo}
template<int KIN, int KST, int NT, int NV, int NTHR>
__device__ __forceinline__ void pack_w(const float* __restrict__ W, float* Wp, int tid) {
    for (int idx = tid; idx < KST * NT * 32; idx += NTHR) {
        int ks  = idx / (NT * 32);
        int rem = idx - ks * NT * 32;
        int nt = rem >> 5, l = rem & 31;
        int k0 = ks * 8 + (l & 3), n = nt * 8 + (l >> 2);
        float w0 = (k0 < KIN && n < NV) ? W[k0 * NV + n] : 0.f;
        float w1 = (k0 + 4 < KIN && n < NV) ? W[(k0 + 4) * NV + n] : 0.f;
        unsigned h0 = f2tf(w0), h1 = f2tf(w1);
        unsigned l0 = f2tf(w0 - __uint_as_float(h0));
        unsigned l1 = f2tf(w1 - __uint_as_float(h1));
        ((float4*)Wp)[idx] = make_float4(__uint_as_float(h0), __uint_as_float(h1),
                                         __uint_as_float(l0), __uint_as_float(l1));
    }
}

// 3-term TF32 mainloop: acc[NT][4] += A(16 rows) @ W-frags
template<int KST, int KP, int NT>
__device__ __forceinline__ void mma_main(const float* __restrict__ Ab,
                                         const float* __restrict__ Wp,
                                         int lane, float acc[][4]) {
    const int g = lane >> 2, tg = lane & 3;
    #pragma unroll
    for (int ks = 0; ks < KST; ks++) {
        float f0 = Ab[g * KP + ks * 8 + tg];
        float f1 = Ab[(g + 8) * KP + ks * 8 + tg];
        float f2 = Ab[g * KP + ks * 8 + tg + 4];
        float f3 = Ab[(g + 8) * KP + ks * 8 + tg + 4];
        unsigned ah0 = f2tf(f0), ah1 = f2tf(f1), ah2 = f2tf(f2), ah3 = f2tf(f3);
        unsigned al0 = f2tf(f0 - __uint_as_float(ah0));
        unsigned al1 = f2tf(f1 - __uint_as_float(ah1));
        unsigned al2 = f2tf(f2 - __uint_as_float(ah2));
        unsigned al3 = f2tf(f3 - __uint_as_float(ah3));
        const float4* wrow = (const float4*)Wp + ks * NT * 32 + lane;
        float4 b[NT];
        #pragma unroll
        for (int nt = 0; nt < NT; nt++) b[nt] = wrow[nt * 32];
        #pragma unroll
        for (int nt = 0; nt < NT; nt++)
            mma8(acc[nt], ah0, ah1, ah2, ah3,
                 __float_as_uint(b[nt].x), __float_as_uint(b[nt].y));
        #pragma unroll
        for (int nt = 0; nt < NT; nt++)
            mma8(acc[nt], al0, al1, al2, al3,
                 __float_as_uint(b[nt].x), __float_as_uint(b[nt].y));
        #pragma unroll
        for (int nt = 0; nt < NT; nt++)
            mma8(acc[nt], ah0, ah1, ah2, ah3,
                 __float_as_uint(b[nt].z), __float_as_uint(b[nt].w));
    }
}

// async copy of one 128/64-row A tile; zero-fills pad + OOB rows
template<int KIN, int KP, int ROWS, int NTHR>
__device__ __forceinline__ void prefetch_tile(const float* __restrict__ A, int M,
                                              int t, float* db, int tid) {
    constexpr int CH = KP / 4;
    const int row0 = t * ROWS;
    for (int idx = tid; idx < ROWS * CH; idx += NTHR) {
        int r = idx / CH, c = idx - r * CH;
        int grow = row0 + r;
        unsigned sa = (unsigned)__cvta_generic_to_shared(db + r * KP + c * 4);
        int nb = 0;
        const float* gs = A;
        if (grow < M) {
            int col = c * 4;
            nb = KIN - col;
            nb = nb < 0 ? 0 : (nb > 4 ? 4 : nb);
            nb *= 4;
            gs = A + (size_t)grow * KIN + (col < KIN ? col : 0);
        }
        asm volatile("cp.async.cg.shared.global [%0], [%1], 16, %2;"
                     :: "r"(sa), "l"(gs), "r"(nb));
    }
    asm volatile("cp.async.commit_group;");
}

// ---------------- standard TF32 GEMM (256 thr, 128-row tiles, dbl-buffered) --
// EPI: 0 store+bias, 1 relu(acc+bias), 3 relu(acc+bias+Ta[src]+Tb[dst]), 4 raw
template<int KIN, int KST, int KP, int NT, int NV, int EPI>
__global__ void __launch_bounds__(256)
tgemm_k(const float* __restrict__ A, const float* __restrict__ W,
        const float* __restrict__ bias, float* __restrict__ C, int M,
        const int* __restrict__ src, const int* __restrict__ dst,
        const float* __restrict__ Ta, const float* __restrict__ Tb) {
    constexpr int WFRAG = KST * NT * 128;
    constexpr int ATILE = 128 * KP;
    extern __shared__ float sm[];
    float* Wp = sm;
    float* As = sm + WFRAG;
    const int tid  = threadIdx.x;
    const int lane = tid & 31, warp = tid >> 5;
    const int g = lane >> 2, tg = lane & 3;

    pack_w<KIN, KST, NT, NV, 256>(W, Wp, tid);

    const int ntile = (M + 127) >> 7;
    if (blockIdx.x >= ntile) return;
    prefetch_tile<KIN, KP, 128, 256>(A, M, blockIdx.x, As, tid);
    __syncthreads();

    int buf = 0;
    for (int t = blockIdx.x; t < ntile; t += gridDim.x) {
        int tn = t + gridDim.x;
        if (tn < ntile) {
            prefetch_tile<KIN, KP, 128, 256>(A, M, tn, As + (buf ^ 1) * ATILE, tid);
            asm volatile("cp.async.wait_group 1;");
        } else {
            asm volatile("cp.async.wait_group 0;");
        }
        __syncthreads();

        const float* Ab = As + buf * ATILE + warp * 16 * KP;
        float acc[NT][4];
        #pragma unroll
        for (int nt = 0; nt < NT; nt++)
            acc[nt][0] = acc[nt][1] = acc[nt][2] = acc[nt][3] = 0.f;

        mma_main<KST, KP, NT>(Ab, Wp, lane, acc);

        int rbase = t * 128 + warp * 16;
        #pragma unroll
        for (int half = 0; half < 2; half++) {
            int row = rbase + g + half * 8;
            bool rok = row < M;
            const float* ta = nullptr; const float* tb = nullptr;
            if (EPI == 3 && rok) {
                ta = Ta + (size_t)src[row] * NV;
                tb = Tb + (size_t)dst[row] * NV;
            }
            #pragma unroll
            for (int nt = 0; nt < NT; nt++) {
                int n = nt * 8 + tg * 2;
                if (rok && n < NV) {
                    float v0 = acc[nt][half * 2 + 0];
                    float v1 = acc[nt][half * 2 + 1];
                    float2* cp = (float2*)(C + (size_t)row * NV + n);
                    if (EPI == 0) {
                        float2 bs = *(const float2*)(bias + n);
                        *cp = make_float2(v0 + bs.x, v1 + bs.y);
                    } else if (EPI == 1) {
                        float2 bs = *(const float2*)(bias + n);
                        *cp = make_float2(fmaxf(v0 + bs.x, 0.f), fmaxf(v1 + bs.y, 0.f));
                    } else if (EPI == 3) {
                        float2 bs = *(const float2*)(bias + n);
                        float2 tav = *(const float2*)(ta + n);
                        float2 tbv = *(const float2*)(tb + n);
                        *cp = make_float2(fmaxf(v0 + bs.x + tav.x + tbv.x, 0.f),
                                          fmaxf(v1 + bs.y + tav.y + tbv.y, 0.f));
                    } else {
                        *cp = make_float2(v0, v1);
                    }
                }
            }
        }
        buf ^= 1;
        __syncthreads();
    }
}

// ---------------- fused edge-update double GEMM ------------------------------
// t = relu(e@W1 + b1 + Ha[src] + Hb[dst])  (smem only)
// e += 0.5 * (t@W2 + b2)
// 128 threads, 64-row tiles; W1/W2 frags packed once; next-A prefetch overlaps GEMM2.
__global__ void __launch_bounds__(128)
fgemm_k(const float* __restrict__ W1, const float* __restrict__ b1,
        const float* __restrict__ W2, const float* __restrict__ b2,
        float* __restrict__ e,
        const int* __restrict__ src, const int* __restrict__ dst,
        const float* __restrict__ Ta, const float* __restrict__ Tb) {
    constexpr int KST = 13, KP = 108, NT = 13, NV = 100, M = Ee;
    constexpr int WFRAG = KST * NT * 128;
    extern __shared__ float sm[];
    float* Wp1 = sm;
    float* Wp2 = sm + WFRAG;
    float* As  = sm + 2 * WFRAG;            // 64*108
    float* Ts  = sm + 2 * WFRAG + 64 * KP;  // 64*108
    const int tid  = threadIdx.x;
    const int lane = tid & 31, warp = tid >> 5;
    const int g = lane >> 2, tg = lane & 3;

    pack_w<100, KST, NT, NV, 128>(W1, Wp1, tid);
    pack_w<100, KST, NT, NV, 128>(W2, Wp2, tid);

    const int ntile = (M + 63) >> 6;
    prefetch_tile<100, KP, 64, 128>(e, M, blockIdx.x, As, tid);
    __syncthreads();

    for (int t = blockIdx.x; t < ntile; t += gridDim.x) {
        asm volatile("cp.async.wait_group 0;");
        __syncthreads();

        const float* Ab = As + warp * 16 * KP;
        float acc[NT][4];
        #pragma unroll
        for (int nt = 0; nt < NT; nt++)
            acc[nt][0] = acc[nt][1] = acc[nt][2] = acc[nt][3] = 0.f;
        mma_main<KST, KP, NT>(Ab, Wp1, lane, acc);
        __syncthreads();   // all warps done reading As

        // prefetch next tile into As (overlaps t-write + GEMM2)
        int tn = t + gridDim.x;
        if (tn < ntile) prefetch_tile<100, KP, 64, 128>(e, M, tn, As, tid);

        // t tile into Ts (+ gathers + bias + relu); zero K-pad cols
        int rbase = t * 64 + warp * 16;
        #pragma unroll
        for (int half = 0; half < 2; half++) {
            int rl = warp * 16 + g + half * 8;
            int row = rbase + g + half * 8;
            bool rok = row < M;
            const float* ta = nullptr; const float* tb = nullptr;
            if (rok) {
                ta = Ta + (size_t)src[row] * NV;
                tb = Tb + (size_t)dst[row] * NV;
            }
            #pragma unroll
            for (int nt = 0; nt < NT; nt++) {
                int n = nt * 8 + tg * 2;
                if (n < NV) {
                    float v0 = 0.f, v1 = 0.f;
                    if (rok) {
                        float2 bs = *(const float2*)(b1 + n);
                        float2 tav = *(const float2*)(ta + n);
                        float2 tbv = *(const float2*)(tb + n);
                        v0 = fmaxf(acc[nt][half * 2 + 0] + bs.x + tav.x + tbv.x, 0.f);
                        v1 = fmaxf(acc[nt][half * 2 + 1] + bs.y + tav.y + tbv.y, 0.f);
                    }
                    *(float2*)(Ts + rl * KP + n) = make_float2(v0, v1);
                }
            }
        }
        for (int idx = tid; idx < 64 * 8; idx += 128) {
            int r = idx >> 3, c = 100 + (idx & 7);
            Ts[r * KP + c] = 0.f;
        }
        __syncthreads();

        const float* Tb2 = Ts + warp * 16 * KP;
        float acc2[NT][4];
        #pragma unroll
        for (int nt = 0; nt < NT; nt++)
            acc2[nt][0] = acc2[nt][1] = acc2[nt][2] = acc2[nt][3] = 0.f;
        mma_main<KST, KP, NT>(Tb2, Wp2, lane, acc2);

        // epilogue: e[row] += 0.5*(acc2 + b2)
        #pragma unroll
        for (int half = 0; half < 2; half++) {
            int row = rbase + g + half * 8;
            if (row < M) {
                #pragma unroll
                for (int nt = 0; nt < NT; nt++) {
                    int n = nt * 8 + tg * 2;
                    if (n < NV) {
                        float2 bs = *(const float2*)(b2 + n);
                        float2* cp = (float2*)(e + (size_t)row * NV + n);
                        float2 old = *cp;
                        *cp = make_float2(
                            fmaf(0.5f, acc2[nt][half * 2 + 0] + bs.x, old.x),
                            fmaf(0.5f, acc2[nt][half * 2 + 1] + bs.y, old.y));
                    }
                }
            }
        }
        __syncthreads();
    }
}

// fused tail: out = relu(o1@w2+b2) @ w3 + b3 per edge
__global__ void __launch_bounds__(256)
final_fused_k(const float* __restrict__ o1,
              const float* __restrict__ w2, const float* __restrict__ b2,
              const float* __restrict__ w3, const float* __restrict__ b3,
              float* __restrict__ out) {
    __shared__ float sw2[50 * 25];
    __shared__ float sw3[50];
    __shared__ float sb2[25];
    __shared__ float sb3[2];
    int t = threadIdx.x;
    for (int i = t; i < 1250; i += 256) sw2[i] = w2[i];
    if (t < 50) sw3[t] = w3[t];
    if (t < 25) sb2[t] = b2[t];
    if (t < 2)  sb3[t] = b3[t];
    __syncthreads();
    int r = blockIdx.x * 256 + t;
    if (r >= Ee) return;
    float a[50];
    const float2* row = (const float2*)(o1 + (size_t)r * 50);
    #pragma unroll
    for (int i = 0; i < 25; i++) { float2 v = row[i]; a[2*i] = v.x; a[2*i+1] = v.y; }
    float out0 = sb3[0], out1 = sb3[1];
    #pragma unroll 5
    for (int j = 0; j < 25; j++) {
        float s = sb2[j];
        #pragma unroll
        for (int k = 0; k < 50; k++) s = fmaf(a[k], sw2[k * 25 + j], s);
        s = fmaxf(s, 0.f);
        out0 = fmaf(s, sw3[2 * j],     out0);
        out1 = fmaf(s, sw3[2 * j + 1], out1);
    }
    out[(size_t)r * 2]     = out0;
    out[(size_t)r * 2 + 1] = out1;
}

// ---------------- launcher ---------------------------------------------------
static inline int cdiv(int a, int b) { return (a + b - 1) / b; }

template<int KIN, int KST, int KP, int NT, int NV, int EPI>
static void launch_tgemm(int M, const float* A, const float* W,
                         const float* bias, float* C,
                         const int* src = nullptr, const int* dst = nullptr,
                         const float* Ta = nullptr, const float* Tb = nullptr) {
    int smem = (KST * NT * 128 + 2 * 128 * KP) * 4;
    cudaFuncSetAttribute(tgemm_k<KIN, KST, KP, NT, NV, EPI>,
                         cudaFuncAttributeMaxDynamicSharedMemorySize, smem);
    int ntile = cdiv(M, 128);
    int grid = ntile < 148 ? ntile : 148;
    tgemm_k<KIN, KST, KP, NT, NV, EPI><<<grid, 256, smem>>>(
        A, W, bias, C, M, src, dst, Ta, Tb);
}

extern "C" void kernel_launch(void* const* d_in, const int* in_sizes, int n_in,
                              void* d_out, int out_size) {
    const float* x        = (const float*)d_in[0];
    const float* edge_attr= (const float*)d_in[1];
    const int*   ei       = (const int*)  d_in[2];
    const float* node_w   = (const float*)d_in[3];
    const float* node_b   = (const float*)d_in[4];
    const float* edge_w   = (const float*)d_in[5];
    const float* edge_b   = (const float*)d_in[6];
    const float* gw1      = (const float*)d_in[7];
    const float* gb1      = (const float*)d_in[8];
    const float* gw2      = (const float*)d_in[9];
    const float* gb2      = (const float*)d_in[10];
    const float* bng      = (const float*)d_in[11];
    const float* bnb      = (const float*)d_in[12];
    const float* ew1      = (const float*)d_in[13];
    const float* eb1      = (const float*)d_in[14];
    const float* ew2      = (const float*)d_in[15];
    const float* eb2      = (const float*)d_in[16];
    const float* mw1      = (const float*)d_in[17];
    const float* mb1      = (const float*)d_in[18];
    const float* mw2      = (const float*)d_in[19];
    const float* mb2      = (const float*)d_in[20];
    const float* mw3      = (const float*)d_in[21];
    const float* mb3      = (const float*)d_in[22];
    float* out = (float*)d_out;

    void* p;
    cudaGetSymbolAddress(&p, g_h);    float* h    = (float*)p;
    cudaGetSymbolAddress(&p, g_e);    float* e    = (float*)p;
    cudaGetSymbolAddress(&p, g_agg);  float* agg  = (float*)p;
    cudaGetSymbolAddress(&p, g_zin);  float* zin  = (float*)p;
    cudaGetSymbolAddress(&p, g_t);    float* t    = (float*)p;
    cudaGetSymbolAddress(&p, g_z);    float* z    = (float*)p;
    cudaGetSymbolAddress(&p, g_Ha);   float* Ha   = (float*)p;
    cudaGetSymbolAddress(&p, g_Hb);   float* Hb   = (float*)p;
    cudaGetSymbolAddress(&p, g_HRa);  float* HRa  = (float*)p;
    cudaGetSymbolAddress(&p, g_HRb);  float* HRb  = (float*)p;
    cudaGetSymbolAddress(&p, g_o1);   float* o1   = (float*)p;
    cudaGetSymbolAddress(&p, g_stats);float* st   = (float*)p;

    const int* src = ei;
    const int* dst = ei + Ee;

    zero2_k<<<cdiv(Nn * Hh, 256), 256>>>(agg, st);
    launch_tgemm<FIN, 8, 68, 13, 100, 0>(Nn, x, node_w, node_b, h);
    launch_tgemm<EIN, 2, 20, 13, 100, 0>(Ee, edge_attr, edge_w, edge_b, e);

    for (int l = 0; l < LL; l++) {
        if (l > 0) zero2_k<<<cdiv(Nn * Hh, 256), 256>>>(agg, st);
        scatter_k<<<Ee / 8, 256>>>(h, e, src, dst, agg);
        add_k<<<cdiv(Nn * Hh, 256), 256>>>(h, agg, zin, Nn * Hh);
        // GINE MLP (launch 6 on first layer -> profiled)
        launch_tgemm<100, 13, 108, 13, 100, 1>(Nn, zin, gw1 + (size_t)l * 10000,
                                               gb1 + l * Hh, t);
        launch_tgemm<100, 13, 108, 13, 100, 0>(Nn, t, gw2 + (size_t)l * 10000,
                                               gb2 + l * Hh, z);
        bn_stats_k<<<cdiv(Nn, 256), 128>>>(z, st);
        hupd_k<<<cdiv(Nn * Hh, 256), 256>>>(h, z, st, bng + l * Hh, bnb + l * Hh);
        // node-level halves of edge MLP
        launch_tgemm<100, 13, 108, 13, 100, 4>(Nn, h, ew1 + (size_t)l * 30000, nullptr, Ha);
        launch_tgemm<100, 13, 108, 13, 100, 4>(Nn, h, ew1 + (size_t)l * 30000 + 10000, nullptr, Hb);
        // fused: t = relu(e@Wc + Ha[src] + Hb[dst] + b1); e += 0.5*(t@W2 + b2)
        {
            int smem = (2 * 13 * 13 * 128 + 2 * 64 * 108) * 4;
            cudaFuncSetAttribute(fgemm_k, cudaFuncAttributeMaxDynamicSharedMemorySize, smem);
            fgemm_k<<<148, 128, smem>>>(ew1 + (size_t)l * 30000 + 20000, eb1 + l * Hh,
                                        ew2 + (size_t)l * 10000, eb2 + l * Hh,
                                        e, src, dst, Ha, Hb);
        }
    }

    // readout
    relu_k<<<cdiv(Nn * Hh, 256), 256>>>(h, zin, Nn * Hh);
    launch_tgemm<100, 13, 108, 7, 50, 4>(Nn, zin, mw1,        nullptr, HRa);
    launch_tgemm<100, 13, 108, 7, 50, 4>(Nn, zin, mw1 + 5000, nullptr, HRb);
    launch_tgemm<100, 13, 108, 7, 50, 3>(Ee, e, mw1 + 10000, mb1, o1, src, dst, HRa, HRb);
    final_fused_k<<<cdiv(Ee, 256), 256>>>(o1, mw2, mb2, mw3, mb3, out);
}

// round 13
// speedup vs baseline: 1.2903x; 1.2880x over previous
#include <cuda_runtime.h>
#include <cuda_bf16.h>
#include <math.h>

#define Nn   50000
#define Ee   500000
#define FIN  64
#define EIN  16
#define Hh   100
#define LL   2
#define BN_EPS 1e-5f

// ---------------- scratch (static device globals; no allocation) -------------
__device__ float g_h   [Nn * Hh];
__device__ float g_e   [(size_t)Ee * Hh];
__device__ float g_agg [Nn * Hh];
__device__ float g_zin [Nn * Hh];
__device__ float g_t   [Nn * Hh];
__device__ float g_z   [Nn * Hh];
__device__ float g_Ha  [Nn * Hh];
__device__ float g_Hb  [Nn * Hh];
__device__ float g_HRa [Nn * 50];
__device__ float g_HRb [Nn * 50];
__device__ float g_o1  [(size_t)Ee * 50];
__device__ float g_stats[2 * Hh];

// ---------------- small kernels ----------------------------------------------
__global__ void zero2_k(float* __restrict__ agg, float* __restrict__ st) {
    int i = blockIdx.x * blockDim.x + threadIdx.x;
    if (i < Nn * Hh) agg[i] = 0.f;
    if (i < 2 * Hh) st[i] = 0.f;
}

__global__ void add_k(const float* __restrict__ a, const float* __restrict__ b,
                      float* __restrict__ c, int n) {
    int i = blockIdx.x * blockDim.x + threadIdx.x;
    if (i < n) c[i] = a[i] + b[i];
}

__global__ void relu_k(const float* __restrict__ a, float* __restrict__ c, int n) {
    int i = blockIdx.x * blockDim.x + threadIdx.x;
    if (i < n) c[i] = fmaxf(a[i], 0.f);
}

__global__ void __launch_bounds__(256)
scatter_k(const float* __restrict__ h, const float* __restrict__ e,
          const int* __restrict__ src, const int* __restrict__ dst,
          float* __restrict__ agg) {
    int ed = blockIdx.x * 8 + (threadIdx.x >> 5);
    int lane = threadIdx.x & 31;
    if (lane >= 25) return;
    int s = src[ed], d = dst[ed];
    float4 hv = ((const float4*)(h + (size_t)s * Hh))[lane];
    float4 ev = ((const float4*)(e + (size_t)ed * Hh))[lane];
    float* ar = agg + (size_t)d * Hh + 4 * lane;
    float m0 = hv.x + ev.x, m1 = hv.y + ev.y, m2 = hv.z + ev.z, m3 = hv.w + ev.w;
    if (m0 > 0.f) atomicAdd(ar + 0, m0);
    if (m1 > 0.f) atomicAdd(ar + 1, m1);
    if (m2 > 0.f) atomicAdd(ar + 2, m2);
    if (m3 > 0.f) atomicAdd(ar + 3, m3);
}

__global__ void bn_stats_k(const float* __restrict__ z, float* __restrict__ stats) {
    int j = threadIdx.x;
    if (j >= Hh) return;
    int r0 = blockIdx.x * 256;
    int r1 = min(r0 + 256, Nn);
    float s = 0.f, ss = 0.f;
    for (int r = r0; r < r1; r++) {
        float v = z[(size_t)r * Hh + j];
        s += v;
        ss = fmaf(v, v, ss);
    }
    atomicAdd(&stats[j], s);
    atomicAdd(&stats[Hh + j], ss);
}

__global__ void hupd_k(float* __restrict__ h, const float* __restrict__ z,
                       const float* __restrict__ stats,
                       const float* __restrict__ gamma, const float* __restrict__ beta) {
    int idx = blockIdx.x * blockDim.x + threadIdx.x;
    if (idx >= Nn * Hh) return;
    int j = idx % Hh;
    float mu  = stats[j] * (1.0f / Nn);
    float var = fmaf(-mu, mu, stats[Hh + j] * (1.0f / Nn));
    float zn  = (z[idx] - mu) * rsqrtf(var + BN_EPS) * gamma[j] + beta[j];
    h[idx] = (h[idx] + fmaxf(zn, 0.f)) * 0.5f;
}

// ---------------- bf16x2 split machinery --------------------------------------
__device__ __forceinline__ void mma16b(float* c, unsigned a0, unsigned a1,
                                       unsigned a2, unsigned a3,
                                       unsigned b0, unsigned b1) {
    asm volatile(
        "mma.sync.aligned.m16n8k16.row.col.f32.bf16.bf16.f32 "
        "{%0,%1,%2,%3}, {%4,%5,%6,%7}, {%8,%9}, {%0,%1,%2,%3};"
        : "+f"(c[0]), "+f"(c[1]), "+f"(c[2]), "+f"(c[3])
        : "r"(a0), "r"(a1), "r"(a2), "r"(a3), "r"(b0), "r"(b1));
}

// split a float2 (k-even, k-odd) into packed bf16x2 hi (truncation) + lo (RN)
__device__ __forceinline__ void split2(float2 p, unsigned& hi, unsigned& lo) {
    unsigned bx = __float_as_uint(p.x), by = __float_as_uint(p.y);
    unsigned h;
    asm("prmt.b32 %0, %1, %2, 0x7632;" : "=r"(h) : "r"(bx), "r"(by));
    float hx = __uint_as_float(bx & 0xFFFF0000u);
    float hy = __uint_as_float(by & 0xFFFF0000u);
    float lx = p.x - hx, ly = p.y - hy;
    unsigned l;
    asm("cvt.rn.bf16x2.f32 %0, %1, %2;" : "=r"(l) : "f"(ly), "f"(lx));  // {lo=lx, hi=ly}
    hi = h; lo = l;
}

// pack W fragments for m16n8k16 with RN hi/lo split:
// uint4 {b0hi, b1hi, b0lo, b1lo};  b0 = {W[k0][n], W[k0+1][n]}, b1 = {W[k0+8][n], W[k0+9][n]}
template<int KIN, int KST, int NT, int NV, int NTHR>
__device__ __forceinline__ void pack_w(const float* __restrict__ W, float* Wp, int tid) {
    for (int idx = tid; idx < KST * NT * 32; idx += NTHR) {
        int ks  = idx / (NT * 32);
        int rem = idx - ks * NT * 32;
        int nt = rem >> 5, l = rem & 31;
        int tg = l & 3, g = l >> 2;
        int n = nt * 8 + g;
        int k0 = ks * 16 + 2 * tg;
        float w[4];
        #pragma unroll
        for (int q = 0; q < 4; q++) {
            int k = k0 + (q >> 1) * 8 + (q & 1);
            w[q] = (k < KIN && n < NV) ? W[k * NV + n] : 0.f;
        }
        float lo[4];
        unsigned hb[2], lb[2];
        #pragma unroll
        for (int q = 0; q < 4; q++) {
            __nv_bfloat16 hq = __float2bfloat16(w[q]);
            lo[q] = w[q] - __bfloat162float(hq);
        }
        #pragma unroll
        for (int pairi = 0; pairi < 2; pairi++) {
            __nv_bfloat162 hh = {__float2bfloat16(w[pairi * 2]),
                                 __float2bfloat16(w[pairi * 2 + 1])};
            __nv_bfloat162 ll = {__float2bfloat16(lo[pairi * 2]),
                                 __float2bfloat16(lo[pairi * 2 + 1])};
            hb[pairi] = *(unsigned*)&hh;
            lb[pairi] = *(unsigned*)&ll;
        }
        ((uint4*)Wp)[idx] = make_uint4(hb[0], hb[1], lb[0], lb[1]);
    }
}

// 3-term bf16x2 mainloop: acc[NT][4] += A(16 rows) @ W-frags
template<int KST, int KP, int NT>
__device__ __forceinline__ void mma_main(const float* __restrict__ Ab,
                                         const float* __restrict__ Wp,
                                         int lane, float acc[][4]) {
    const int g = lane >> 2, tg = lane & 3;
    #pragma unroll
    for (int ks = 0; ks < KST; ks++) {
        int k0 = ks * 16 + 2 * tg;
        float2 p0 = *(const float2*)(Ab + g * KP + k0);
        float2 p1 = *(const float2*)(Ab + (g + 8) * KP + k0);
        float2 p2 = *(const float2*)(Ab + g * KP + k0 + 8);
        float2 p3 = *(const float2*)(Ab + (g + 8) * KP + k0 + 8);
        unsigned ah0, ah1, ah2, ah3, al0, al1, al2, al3;
        split2(p0, ah0, al0);
        split2(p1, ah1, al1);
        split2(p2, ah2, al2);
        split2(p3, ah3, al3);
        const uint4* wrow = (const uint4*)Wp + ks * NT * 32 + lane;
        uint4 b[NT];
        #pragma unroll
        for (int nt = 0; nt < NT; nt++) b[nt] = wrow[nt * 32];
        #pragma unroll
        for (int nt = 0; nt < NT; nt++)
            mma16b(acc[nt], ah0, ah1, ah2, ah3, b[nt].x, b[nt].y);   // hi*hi
        #pragma unroll
        for (int nt = 0; nt < NT; nt++)
            mma16b(acc[nt], al0, al1, al2, al3, b[nt].x, b[nt].y);   // lo*hi
        #pragma unroll
        for (int nt = 0; nt < NT; nt++)
            mma16b(acc[nt], ah0, ah1, ah2, ah3, b[nt].z, b[nt].w);   // hi*lo
    }
}

// async copy of one A tile; zero-fills pad + OOB rows
template<int KIN, int KP, int ROWS, int NTHR>
__device__ __forceinline__ void prefetch_tile(const float* __restrict__ A, int M,
                                              int t, float* db, int tid) {
    constexpr int CH = KP / 4;
    const int row0 = t * ROWS;
    for (int idx = tid; idx < ROWS * CH; idx += NTHR) {
        int r = idx / CH, c = idx - r * CH;
        int grow = row0 + r;
        unsigned sa = (unsigned)__cvta_generic_to_shared(db + r * KP + c * 4);
        int nb = 0;
        const float* gs = A;
        if (grow < M) {
            int col = c * 4;
            nb = KIN - col;
            nb = nb < 0 ? 0 : (nb > 4 ? 4 : nb);
            nb *= 4;
            gs = A + (size_t)grow * KIN + (col < KIN ? col : 0);
        }
        asm volatile("cp.async.cg.shared.global [%0], [%1], 16, %2;"
                     :: "r"(sa), "l"(gs), "r"(nb));
    }
    asm volatile("cp.async.commit_group;");
}

// ---------------- standard bf16x2 GEMM (256 thr, 128-row tiles, dbl-buffered) -
// EPI: 0 store+bias, 1 relu(acc+bias), 3 relu(acc+bias+Ta[src]+Tb[dst]), 4 raw
template<int KIN, int KST, int KP, int NT, int NV, int EPI>
__global__ void __launch_bounds__(256)
tgemm_k(const float* __restrict__ A, const float* __restrict__ W,
        const float* __restrict__ bias, float* __restrict__ C, int M,
        const int* __restrict__ src, const int* __restrict__ dst,
        const float* __restrict__ Ta, const float* __restrict__ Tb) {
    constexpr int WFRAG = KST * NT * 128;
    constexpr int ATILE = 128 * KP;
    extern __shared__ float sm[];
    float* Wp = sm;
    float* As = sm + WFRAG;
    const int tid  = threadIdx.x;
    const int lane = tid & 31, warp = tid >> 5;
    const int g = lane >> 2, tg = lane & 3;

    pack_w<KIN, KST, NT, NV, 256>(W, Wp, tid);

    const int ntile = (M + 127) >> 7;
    if (blockIdx.x >= ntile) return;
    prefetch_tile<KIN, KP, 128, 256>(A, M, blockIdx.x, As, tid);
    __syncthreads();

    int buf = 0;
    for (int t = blockIdx.x; t < ntile; t += gridDim.x) {
        int tn = t + gridDim.x;
        if (tn < ntile) {
            prefetch_tile<KIN, KP, 128, 256>(A, M, tn, As + (buf ^ 1) * ATILE, tid);
            asm volatile("cp.async.wait_group 1;");
        } else {
            asm volatile("cp.async.wait_group 0;");
        }
        __syncthreads();

        const float* Ab = As + buf * ATILE + warp * 16 * KP;
        float acc[NT][4];
        #pragma unroll
        for (int nt = 0; nt < NT; nt++)
            acc[nt][0] = acc[nt][1] = acc[nt][2] = acc[nt][3] = 0.f;

        mma_main<KST, KP, NT>(Ab, Wp, lane, acc);

        int rbase = t * 128 + warp * 16;
        #pragma unroll
        for (int half = 0; half < 2; half++) {
            int row = rbase + g + half * 8;
            bool rok = row < M;
            const float* ta = nullptr; const float* tb = nullptr;
            if (EPI == 3 && rok) {
                ta = Ta + (size_t)src[row] * NV;
                tb = Tb + (size_t)dst[row] * NV;
            }
            #pragma unroll
            for (int nt = 0; nt < NT; nt++) {
                int n = nt * 8 + tg * 2;
                if (rok && n < NV) {
                    float v0 = acc[nt][half * 2 + 0];
                    float v1 = acc[nt][half * 2 + 1];
                    float2* cp = (float2*)(C + (size_t)row * NV + n);
                    if (EPI == 0) {
                        float2 bs = *(const float2*)(bias + n);
                        *cp = make_float2(v0 + bs.x, v1 + bs.y);
                    } else if (EPI == 1) {
                        float2 bs = *(const float2*)(bias + n);
                        *cp = make_float2(fmaxf(v0 + bs.x, 0.f), fmaxf(v1 + bs.y, 0.f));
                    } else if (EPI == 3) {
                        float2 bs = *(const float2*)(bias + n);
                        float2 tav = *(const float2*)(ta + n);
                        float2 tbv = *(const float2*)(tb + n);
                        *cp = make_float2(fmaxf(v0 + bs.x + tav.x + tbv.x, 0.f),
                                          fmaxf(v1 + bs.y + tav.y + tbv.y, 0.f));
                    } else {
                        *cp = make_float2(v0, v1);
                    }
                }
            }
        }
        buf ^= 1;
        __syncthreads();
    }
}

// ---------------- fused edge-update double GEMM (bf16x2) ----------------------
// t = relu(e@W1 + b1 + Ha[src] + Hb[dst])  (smem only)
// e += 0.5 * (t@W2 + b2)
// 256 threads, 128-row tiles; W1/W2 frags packed once; prefetch overlaps GEMM2.
__global__ void __launch_bounds__(256)
fgemm_k(const float* __restrict__ W1, const float* __restrict__ b1,
        const float* __restrict__ W2, const float* __restrict__ b2,
        float* __restrict__ e,
        const int* __restrict__ src, const int* __restrict__ dst,
        const float* __restrict__ Ta, const float* __restrict__ Tb) {
    constexpr int KST = 7, KP = 116, NT = 13, NV = 100, M = Ee;
    constexpr int WFRAG = KST * NT * 128;
    extern __shared__ float sm[];
    float* Wp1 = sm;
    float* Wp2 = sm + WFRAG;
    float* As  = sm + 2 * WFRAG;             // 128*116
    float* Ts  = sm + 2 * WFRAG + 128 * KP;  // 128*116
    const int tid  = threadIdx.x;
    const int lane = tid & 31, warp = tid >> 5;
    const int g = lane >> 2, tg = lane & 3;

    pack_w<100, KST, NT, NV, 256>(W1, Wp1, tid);
    pack_w<100, KST, NT, NV, 256>(W2, Wp2, tid);

    const int ntile = (M + 127) >> 7;
    prefetch_tile<100, KP, 128, 256>(e, M, blockIdx.x, As, tid);
    __syncthreads();

    for (int t = blockIdx.x; t < ntile; t += gridDim.x) {
        asm volatile("cp.async.wait_group 0;");
        __syncthreads();

        const float* Ab = As + warp * 16 * KP;
        float acc[NT][4];
        #pragma unroll
        for (int nt = 0; nt < NT; nt++)
            acc[nt][0] = acc[nt][1] = acc[nt][2] = acc[nt][3] = 0.f;
        mma_main<KST, KP, NT>(Ab, Wp1, lane, acc);
        __syncthreads();   // all warps done reading As

        // prefetch next tile into As (overlaps t-write + GEMM2)
        int tn = t + gridDim.x;
        if (tn < ntile) prefetch_tile<100, KP, 128, 256>(e, M, tn, As, tid);

        // t tile into Ts (+ gathers + bias + relu); zero K-pad cols
        int rbase = t * 128 + warp * 16;
        #pragma unroll
        for (int half = 0; half < 2; half++) {
            int rl = warp * 16 + g + half * 8;
            int row = rbase + g + half * 8;
            bool rok = row < M;
            const float* ta = nullptr; const float* tb = nullptr;
            if (rok) {
                ta = Ta + (size_t)src[row] * NV;
                tb = Tb + (size_t)dst[row] * NV;
            }
            #pragma unroll
            for (int nt = 0; nt < NT; nt++) {
                int n = nt * 8 + tg * 2;
                if (n < NV) {
                    float v0 = 0.f, v1 = 0.f;
                    if (rok) {
                        float2 bs = *(const float2*)(b1 + n);
                        float2 tav = *(const float2*)(ta + n);
                        float2 tbv = *(const float2*)(tb + n);
                        v0 = fmaxf(acc[nt][half * 2 + 0] + bs.x + tav.x + tbv.x, 0.f);
                        v1 = fmaxf(acc[nt][half * 2 + 1] + bs.y + tav.y + tbv.y, 0.f);
                    }
                    *(float2*)(Ts + rl * KP + n) = make_float2(v0, v1);
                }
            }
        }
        for (int idx = tid; idx < 128 * (KP - 100); idx += 256) {
            int r = idx / (KP - 100), c = 100 + idx % (KP - 100);
            Ts[r * KP + c] = 0.f;
        }
        __syncthreads();

        const float* Tbb = Ts + warp * 16 * KP;
        float acc2[NT][4];
        #pragma unroll
        for (int nt = 0; nt < NT; nt++)
            acc2[nt][0] = acc2[nt][1] = acc2[nt][2] = acc2[nt][3] = 0.f;
        mma_main<KST, KP, NT>(Tbb, Wp2, lane, acc2);

        // epilogue: e[row] += 0.5*(acc2 + b2)  (old e re-read from L2)
        #pragma unroll
        for (int half = 0; half < 2; half++) {
            int row = rbase + g + half * 8;
            if (row < M) {
                #pragma unroll
                for (int nt = 0; nt < NT; nt++) {
                    int n = nt * 8 + tg * 2;
                    if (n < NV) {
                        float2 bs = *(const float2*)(b2 + n);
                        float2* cp = (float2*)(e + (size_t)row * NV + n);
                        float2 old = *cp;
                        *cp = make_float2(
                            fmaf(0.5f, acc2[nt][half * 2 + 0] + bs.x, old.x),
                            fmaf(0.5f, acc2[nt][half * 2 + 1] + bs.y, old.y));
                    }
                }
            }
        }
        __syncthreads();   // Ts reads done before next-iter overwrite
    }
}

// fused tail: out = relu(o1@w2+b2) @ w3 + b3 per edge
__global__ void __launch_bounds__(256)
final_fused_k(const float* __restrict__ o1,
              const float* __restrict__ w2, const float* __restrict__ b2,
              const float* __restrict__ w3, const float* __restrict__ b3,
              float* __restrict__ out) {
    __shared__ float sw2[50 * 25];
    __shared__ float sw3[50];
    __shared__ float sb2[25];
    __shared__ float sb3[2];
    int t = threadIdx.x;
    for (int i = t; i < 1250; i += 256) sw2[i] = w2[i];
    if (t < 50) sw3[t] = w3[t];
    if (t < 25) sb2[t] = b2[t];
    if (t < 2)  sb3[t] = b3[t];
    __syncthreads();
    int r = blockIdx.x * 256 + t;
    if (r >= Ee) return;
    float a[50];
    const float2* row = (const float2*)(o1 + (size_t)r * 50);
    #pragma unroll
    for (int i = 0; i < 25; i++) { float2 v = row[i]; a[2*i] = v.x; a[2*i+1] = v.y; }
    float out0 = sb3[0], out1 = sb3[1];
    #pragma unroll 5
    for (int j = 0; j < 25; j++) {
        float s = sb2[j];
        #pragma unroll
        for (int k = 0; k < 50; k++) s = fmaf(a[k], sw2[k * 25 + j], s);
        s = fmaxf(s, 0.f);
        out0 = fmaf(s, sw3[2 * j],     out0);
        out1 = fmaf(s, sw3[2 * j + 1], out1);
    }
    out[(size_t)r * 2]     = out0;
    out[(size_t)r * 2 + 1] = out1;
}

// ---------------- launcher ---------------------------------------------------
static inline int cdiv(int a, int b) { return (a + b - 1) / b; }

template<int KIN, int KST, int KP, int NT, int NV, int EPI>
static void launch_tgemm(int M, const float* A, const float* W,
                         const float* bias, float* C,
                         const int* src = nullptr, const int* dst = nullptr,
                         const float* Ta = nullptr, const float* Tb = nullptr) {
    int smem = (KST * NT * 128 + 2 * 128 * KP) * 4;
    cudaFuncSetAttribute(tgemm_k<KIN, KST, KP, NT, NV, EPI>,
                         cudaFuncAttributeMaxDynamicSharedMemorySize, smem);
    int ntile = cdiv(M, 128);
    int grid = ntile < 148 ? ntile : 148;
    tgemm_k<KIN, KST, KP, NT, NV, EPI><<<grid, 256, smem>>>(
        A, W, bias, C, M, src, dst, Ta, Tb);
}

extern "C" void kernel_launch(void* const* d_in, const int* in_sizes, int n_in,
                              void* d_out, int out_size) {
    const float* x        = (const float*)d_in[0];
    const float* edge_attr= (const float*)d_in[1];
    const int*   ei       = (const int*)  d_in[2];
    const float* node_w   = (const float*)d_in[3];
    const float* node_b   = (const float*)d_in[4];
    const float* edge_w   = (const float*)d_in[5];
    const float* edge_b   = (const float*)d_in[6];
    const float* gw1      = (const float*)d_in[7];
    const float* gb1      = (const float*)d_in[8];
    const float* gw2      = (const float*)d_in[9];
    const float* gb2      = (const float*)d_in[10];
    const float* bng      = (const float*)d_in[11];
    const float* bnb      = (const float*)d_in[12];
    const float* ew1      = (const float*)d_in[13];
    const float* eb1      = (const float*)d_in[14];
    const float* ew2      = (const float*)d_in[15];
    const float* eb2      = (const float*)d_in[16];
    const float* mw1      = (const float*)d_in[17];
    const float* mb1      = (const float*)d_in[18];
    const float* mw2      = (const float*)d_in[19];
    const float* mb2      = (const float*)d_in[20];
    const float* mw3      = (const float*)d_in[21];
    const float* mb3      = (const float*)d_in[22];
    float* out = (float*)d_out;

    void* p;
    cudaGetSymbolAddress(&p, g_h);    float* h    = (float*)p;
    cudaGetSymbolAddress(&p, g_e);    float* e    = (float*)p;
    cudaGetSymbolAddress(&p, g_agg);  float* agg  = (float*)p;
    cudaGetSymbolAddress(&p, g_zin);  float* zin  = (float*)p;
    cudaGetSymbolAddress(&p, g_t);    float* t    = (float*)p;
    cudaGetSymbolAddress(&p, g_z);    float* z    = (float*)p;
    cudaGetSymbolAddress(&p, g_Ha);   float* Ha   = (float*)p;
    cudaGetSymbolAddress(&p, g_Hb);   float* Hb   = (float*)p;
    cudaGetSymbolAddress(&p, g_HRa);  float* HRa  = (float*)p;
    cudaGetSymbolAddress(&p, g_HRb);  float* HRb  = (float*)p;
    cudaGetSymbolAddress(&p, g_o1);   float* o1   = (float*)p;
    cudaGetSymbolAddress(&p, g_stats);float* st   = (float*)p;

    const int* src = ei;
    const int* dst = ei + Ee;

    zero2_k<<<cdiv(Nn * Hh, 256), 256>>>(agg, st);
    launch_tgemm<FIN, 4, 68, 13, 100, 0>(Nn, x, node_w, node_b, h);
    launch_tgemm<EIN, 1, 20, 13, 100, 0>(Ee, edge_attr, edge_w, edge_b, e);

    for (int l = 0; l < LL; l++) {
        if (l > 0) zero2_k<<<cdiv(Nn * Hh, 256), 256>>>(agg, st);
        scatter_k<<<Ee / 8, 256>>>(h, e, src, dst, agg);
        add_k<<<cdiv(Nn * Hh, 256), 256>>>(h, agg, zin, Nn * Hh);
        // GINE MLP
        launch_tgemm<100, 7, 116, 13, 100, 1>(Nn, zin, gw1 + (size_t)l * 10000,
                                              gb1 + l * Hh, t);
        launch_tgemm<100, 7, 116, 13, 100, 0>(Nn, t, gw2 + (size_t)l * 10000,
                                              gb2 + l * Hh, z);
        bn_stats_k<<<cdiv(Nn, 256), 128>>>(z, st);
        hupd_k<<<cdiv(Nn * Hh, 256), 256>>>(h, z, st, bng + l * Hh, bnb + l * Hh);
        // node-level halves of edge MLP
        launch_tgemm<100, 7, 116, 13, 100, 4>(Nn, h, ew1 + (size_t)l * 30000, nullptr, Ha);
        launch_tgemm<100, 7, 116, 13, 100, 4>(Nn, h, ew1 + (size_t)l * 30000 + 10000, nullptr, Hb);
        // fused: t = relu(e@Wc + Ha[src] + Hb[dst] + b1); e += 0.5*(t@W2 + b2)
        {
            int smem = (2 * 7 * 13 * 128 + 2 * 128 * 116) * 4;
            cudaFuncSetAttribute(fgemm_k, cudaFuncAttributeMaxDynamicSharedMemorySize, smem);
            fgemm_k<<<148, 256, smem>>>(ew1 + (size_t)l * 30000 + 20000, eb1 + l * Hh,
                                        ew2 + (size_t)l * 10000, eb2 + l * Hh,
                                        e, src, dst, Ha, Hb);
        }
    }

    // readout (node-level decomposition of mlp_w1)
    relu_k<<<cdiv(Nn * Hh, 256), 256>>>(h, zin, Nn * Hh);
    launch_tgemm<100, 7, 116, 7, 50, 4>(Nn, zin, mw1,        nullptr, HRa);
    launch_tgemm<100, 7, 116, 7, 50, 4>(Nn, zin, mw1 + 5000, nullptr, HRb);
    launch_tgemm<100, 7, 116, 7, 50, 3>(Ee, e, mw1 + 10000, mb1, o1, src, dst, HRa, HRb);
    final_fused_k<<<cdiv(Ee, 256), 256>>>(o1, mw2, mb2, mw3, mb3, out);
}